// round 10
// baseline (speedup 1.0000x reference)
#include <cuda_runtime.h>

// LDDMM Hamiltonian evolve, B=1, N=8192, D=3, sigma=0.1
// out[0:3N]  = -dH/dq = 400 * sum_j K_ij <p_i,p_j> (q_i - q_j)
// out[3N:6N] =  dH/dp = 2   * sum_j K_ij p_j,   K_ij = exp(-100 |q_i-q_j|^2)
//
// R10: 8x8x8 Morton binning, d2 > 0.20 culling at CELL grain but iteration
// at BLOCK grain: per block take the contiguous pair range spanning the
// first..last surviving cell -> long dense unrolled runs (14 packed f32x2
// ops per 2 j at the FFMA2 rt=3 floor), no per-cell inner-loop overhead.

#define NPTS   8192
#define NCELLS 512
#define NBLOCKS 64
#define NHB    16
#define HBPTS  (NPTS / NHB)      // 512
#define PADMAX (NPTS + NCELLS)   // 8704 = 68*128
#define TI     128
#define JS     16
#define GXMAIN (PADMAX / TI)     // 68
#define HALFSZ (NPTS * 3)
#define CAP    128               // smem pair capacity per chunk
#define CKER   (-144.26950408889634f)  // -100*log2(e)
#define D2CUT  0.20f

__device__ int   g_cell[NPTS];
__device__ int   g_bh[NHB * NCELLS];
__device__ int   g_boff[NHB * NCELLS];
__device__ int   g_cps[NCELLS + 1];
__device__ int   g_tot;
__device__ float g_pts[(size_t)PADMAX * 8];

typedef unsigned long long u64;

__device__ __forceinline__ u64 pack2(float lo, float hi) {
    u64 r; asm("mov.b64 %0, {%1, %2};" : "=l"(r) : "f"(lo), "f"(hi)); return r;
}
__device__ __forceinline__ void unpack2(u64 v, float& lo, float& hi) {
    asm("mov.b64 {%0, %1}, %2;" : "=f"(lo), "=f"(hi) : "l"(v));
}
__device__ __forceinline__ u64 fma2(u64 a, u64 b, u64 c) {
    u64 r; asm("fma.rn.f32x2 %0, %1, %2, %3;" : "=l"(r) : "l"(a), "l"(b), "l"(c)); return r;
}
__device__ __forceinline__ u64 add2(u64 a, u64 b) {
    u64 r; asm("add.rn.f32x2 %0, %1, %2;" : "=l"(r) : "l"(a), "l"(b)); return r;
}
__device__ __forceinline__ u64 mul2(u64 a, u64 b) {
    u64 r; asm("mul.rn.f32x2 %0, %1, %2;" : "=l"(r) : "l"(a), "l"(b)); return r;
}
__device__ __forceinline__ u64 ex2_2(u64 x) {
    u64 r;
    asm("{\n\t.reg .f32 l, h;\n\t"
        "mov.b64 {l, h}, %1;\n\t"
        "ex2.approx.ftz.f32 l, l;\n\t"
        "ex2.approx.ftz.f32 h, h;\n\t"
        "mov.b64 %0, {l, h};\n\t}" : "=l"(r) : "l"(x));
    return r;
}
__device__ __forceinline__ float fast_ex2(float x) {
    float y; asm("ex2.approx.ftz.f32 %0, %1;" : "=f"(y) : "f"(x)); return y;
}

__device__ __forceinline__ int cell_morton(int cx, int cy, int cz) {
    return (cx & 1) | ((cy & 1) << 1) | ((cz & 1) << 2)
         | ((cx & 2) << 2) | ((cy & 2) << 3) | ((cz & 2) << 4)
         | ((cx & 4) << 4) | ((cy & 4) << 5) | ((cz & 4) << 6);
}
__device__ __forceinline__ void cell_decode(int c, int& cx, int& cy, int& cz) {
    cx = (c & 1) | ((c >> 2) & 2) | ((c >> 4) & 4);
    cy = ((c >> 1) & 1) | ((c >> 3) & 2) | ((c >> 5) & 4);
    cz = ((c >> 2) & 1) | ((c >> 4) & 2) | ((c >> 6) & 4);
}
__device__ __forceinline__ float boxgap2(
    float lox, float hix, float loy, float hiy, float loz, float hiz,
    float blox, float bhix, float bloy, float bhiy, float bloz, float bhiz) {
    float gx = fmaxf(0.f, fmaxf(blox - hix, lox - bhix));
    float gy = fmaxf(0.f, fmaxf(bloy - hiy, loy - bhiy));
    float gz = fmaxf(0.f, fmaxf(bloz - hiz, loz - bhiz));
    return gx * gx + gy * gy + gz * gz;
}

// ---- stage 1: cellid + per-block histogram + zero out ----
__global__ __launch_bounds__(HBPTS)
void k_hist(const float* __restrict__ q, float* __restrict__ out) {
    __shared__ int h[NCELLS];
    const int tid = threadIdx.x;
    const int i = blockIdx.x * HBPTS + tid;
    h[tid] = 0;

    const int v = blockIdx.x * HBPTS + tid;
    reinterpret_cast<float4*>(out)[v] = make_float4(0.f, 0.f, 0.f, 0.f);
    if (v < 4096)
        reinterpret_cast<float4*>(out)[v + 8192] = make_float4(0.f, 0.f, 0.f, 0.f);
    __syncthreads();

    const float x = q[i * 3 + 0], y = q[i * 3 + 1], z = q[i * 3 + 2];
    const int cx = min(7, max(0, (int)(x * 8.0f)));
    const int cy = min(7, max(0, (int)(y * 8.0f)));
    const int cz = min(7, max(0, (int)(z * 8.0f)));
    const int m = cell_morton(cx, cy, cz);
    g_cell[i] = m;
    atomicAdd(&h[m], 1);
    __syncthreads();
    g_bh[blockIdx.x * NCELLS + tid] = h[tid];
}

// ---- stage 2: scan + per-(block,cell) bases + dummy padding ----
__global__ __launch_bounds__(NCELLS)
void k_scan() {
    __shared__ int s[NCELLS];
    const int t = threadIdx.x;

    int part[NHB];
    int cnt = 0;
#pragma unroll
    for (int b = 0; b < NHB; b++) {
        part[b] = cnt;
        cnt += g_bh[b * NCELLS + t];
    }
    const int pc = (cnt + 1) >> 1;
    s[t] = pc;
    __syncthreads();
    for (int off = 1; off < NCELLS; off <<= 1) {
        int v = (t >= off) ? s[t - off] : 0;
        __syncthreads();
        s[t] += v;
        __syncthreads();
    }
    const int excl = s[t] - pc;
    g_cps[t] = excl;
    if (t == NCELLS - 1) {
        g_cps[NCELLS] = s[t];
        g_tot = 2 * s[t];
    }
    const int base = 2 * excl;
#pragma unroll
    for (int b = 0; b < NHB; b++)
        g_boff[b * NCELLS + t] = base + part[b];

    if (cnt & 1) {
        float4* P = reinterpret_cast<float4*>(g_pts);
        const int slot = base + cnt;
        P[slot * 2 + 0] = make_float4(1000.f, 1000.f, 1000.f, CKER * 3.0e6f);
        P[slot * 2 + 1] = make_float4(0.f, 0.f, 0.f, __int_as_float(-1));
    }
}

// ---- stage 3: scatter (rank via smem atomic; within-cell order is
// run-varying -> output noise ~1e-7, same class as the out[] atomics) ----
__global__ __launch_bounds__(HBPTS)
void k_scatter(const float* __restrict__ q, const float* __restrict__ mom) {
    __shared__ int ctr[NCELLS];
    const int tid = threadIdx.x;
    const int i = blockIdx.x * HBPTS + tid;
    ctr[tid] = 0;
    __syncthreads();

    const int c = g_cell[i];
    const int rank = atomicAdd(&ctr[c], 1);
    const int slot = g_boff[blockIdx.x * NCELLS + c] + rank;

    const float cqx = q[i * 3 + 0] - 0.5f;
    const float cqy = q[i * 3 + 1] - 0.5f;
    const float cqz = q[i * 3 + 2] - 0.5f;
    const float sj = CKER * (cqx * cqx + cqy * cqy + cqz * cqz);
    float4* P = reinterpret_cast<float4*>(g_pts);
    P[slot * 2 + 0] = make_float4(cqx, cqy, cqz, sj);
    P[slot * 2 + 1] = make_float4(mom[i * 3 + 0], mom[i * 3 + 1],
                                  mom[i * 3 + 2], __int_as_float(i));
}

// ---- main kernel ----
__global__ __launch_bounds__(TI)
void k_main(float* __restrict__ out) {
    __shared__ __align__(16) u64 s[CAP * 6];
    __shared__ __align__(16) u64 sz[CAP];
    __shared__ float sbb[2][3][4];

    const int tid = threadIdx.x;
    const int wid = tid >> 5;
    const int i = blockIdx.x * TI + tid;
    const int tot = g_tot;
    const float4* P = reinterpret_cast<const float4*>(g_pts);

    const float4 a0 = P[(size_t)i * 2 + 0];
    const float4 a1 = P[(size_t)i * 2 + 1];
    const float cqx = a0.x, cqy = a0.y, cqz = a0.z;
    const float px = a1.x, py = a1.y, pz = a1.z;
    const int orig = __float_as_int(a1.w);
    const bool use = (i < tot) && (orig >= 0);

    {
        float vx[3] = {use ? cqx : 1e30f, use ? cqy : 1e30f, use ? cqz : 1e30f};
        float wx[3] = {use ? cqx : -1e30f, use ? cqy : -1e30f, use ? cqz : -1e30f};
#pragma unroll
        for (int k = 0; k < 3; k++) {
#pragma unroll
            for (int o = 16; o; o >>= 1) {
                vx[k] = fminf(vx[k], __shfl_xor_sync(0xFFFFFFFFu, vx[k], o));
                wx[k] = fmaxf(wx[k], __shfl_xor_sync(0xFFFFFFFFu, wx[k], o));
            }
            if ((tid & 31) == 0) { sbb[0][k][wid] = vx[k]; sbb[1][k][wid] = wx[k]; }
        }
    }
    __syncthreads();
    const float ilox = fminf(fminf(sbb[0][0][0], sbb[0][0][1]), fminf(sbb[0][0][2], sbb[0][0][3]));
    const float iloy = fminf(fminf(sbb[0][1][0], sbb[0][1][1]), fminf(sbb[0][1][2], sbb[0][1][3]));
    const float iloz = fminf(fminf(sbb[0][2][0], sbb[0][2][1]), fminf(sbb[0][2][2], sbb[0][2][3]));
    const float ihix = fmaxf(fmaxf(sbb[1][0][0], sbb[1][0][1]), fmaxf(sbb[1][0][2], sbb[1][0][3]));
    const float ihiy = fmaxf(fmaxf(sbb[1][1][0], sbb[1][1][1]), fmaxf(sbb[1][1][2], sbb[1][1][3]));
    const float ihiz = fmaxf(fmaxf(sbb[1][2][0], sbb[1][2][1]), fmaxf(sbb[1][2][2], sbb[1][2][3]));

    const u64 M2X = pack2(-2.0f * CKER * cqx, -2.0f * CKER * cqx);
    const u64 M2Y = pack2(-2.0f * CKER * cqy, -2.0f * CKER * cqy);
    const u64 M2Z = pack2(-2.0f * CKER * cqz, -2.0f * CKER * cqz);
    const u64 PXX = pack2(px, px), PYY = pack2(py, py), PZZ = pack2(pz, pz);

    u64 B0 = 0, B1 = 0, B2 = 0, A0 = 0, A1 = 0, A2 = 0, W = 0;

    for (int b = blockIdx.y; b < NBLOCKS; b += JS) {
        // Cell-grain cull, block-grain iteration: contiguous pair range
        // spanning first..last surviving cell of this block.
        int cLo = -1, cHi = -1;
#pragma unroll
        for (int cc = 0; cc < 8; cc++) {
            const int c = b * 8 + cc;
            int cx, cy, cz;
            cell_decode(c, cx, cy, cz);
            const float clox = cx * 0.125f - 0.5f;
            const float cloy = cy * 0.125f - 0.5f;
            const float cloz = cz * 0.125f - 0.5f;
            if (boxgap2(ilox, ihix, iloy, ihiy, iloz, ihiz,
                        clox, clox + 0.125f, cloy, cloy + 0.125f,
                        cloz, cloz + 0.125f) <= D2CUT) {
                if (cLo < 0) cLo = cc;
                cHi = cc;
            }
        }
        if (cLo < 0) continue;

        int ps = __ldg(&g_cps[b * 8 + cLo]);
        const int pe = __ldg(&g_cps[b * 8 + cHi + 1]);

        while (ps < pe) {
            const int n = min(pe - ps, CAP);
            for (int t = tid; t < n; t += TI) {
                const int pp = ps + t;
                const float4 j0a = P[(size_t)(2 * pp) * 2 + 0];
                const float4 j0b = P[(size_t)(2 * pp) * 2 + 1];
                const float4 j1a = P[(size_t)(2 * pp + 1) * 2 + 0];
                const float4 j1b = P[(size_t)(2 * pp + 1) * 2 + 1];
                s[t * 6 + 0] = pack2(j0a.x, j1a.x);
                s[t * 6 + 1] = pack2(j0a.y, j1a.y);
                s[t * 6 + 2] = pack2(j0a.z, j1a.z);
                s[t * 6 + 3] = pack2(j0a.w, j1a.w);
                s[t * 6 + 4] = pack2(j0b.x, j1b.x);
                s[t * 6 + 5] = pack2(j0b.y, j1b.y);
                sz[t]        = pack2(j0b.z, j1b.z);
            }
            __syncthreads();

#pragma unroll 2
            for (int p = 0; p < n; p++) {
                const ulonglong2 w0 = *reinterpret_cast<const ulonglong2*>(&s[p * 6 + 0]);
                const ulonglong2 w1 = *reinterpret_cast<const ulonglong2*>(&s[p * 6 + 2]);
                const ulonglong2 w2 = *reinterpret_cast<const ulonglong2*>(&s[p * 6 + 4]);
                const u64 mz = sz[p];
                const u64 jx = w0.x, jy = w0.y, jz = w1.x, sj = w1.y;
                const u64 mx = w2.x, my = w2.y;

                u64 t = fma2(jx, M2X, sj);
                t = fma2(jy, M2Y, t);
                t = fma2(jz, M2Z, t);
                const u64 K = ex2_2(t);

                const u64 pd = fma2(PXX, mx, fma2(PYY, my, mul2(PZZ, mz)));

                B0 = fma2(K, mx, B0);
                B1 = fma2(K, my, B1);
                B2 = fma2(K, mz, B2);

                const u64 w = mul2(K, pd);
                W  = add2(W, w);
                A0 = fma2(w, jx, A0);
                A1 = fma2(w, jy, A1);
                A2 = fma2(w, jz, A2);
            }
            __syncthreads();
            ps += n;
        }
    }

    if (use) {
        const float Ei = fast_ex2(CKER * (cqx * cqx + cqy * cqy + cqz * cqz));
        const float eq = 400.0f * Ei, ep = 2.0f * Ei;
        float l, h, Ws, A0s, A1s, A2s, B0s, B1s, B2s;
        unpack2(W,  l, h); Ws  = l + h;
        unpack2(A0, l, h); A0s = l + h;
        unpack2(A1, l, h); A1s = l + h;
        unpack2(A2, l, h); A2s = l + h;
        unpack2(B0, l, h); B0s = l + h;
        unpack2(B1, l, h); B1s = l + h;
        unpack2(B2, l, h); B2s = l + h;
        atomicAdd(&out[orig * 3 + 0], eq * fmaf(Ws, cqx, -A0s));
        atomicAdd(&out[orig * 3 + 1], eq * fmaf(Ws, cqy, -A1s));
        atomicAdd(&out[orig * 3 + 2], eq * fmaf(Ws, cqz, -A2s));
        atomicAdd(&out[HALFSZ + orig * 3 + 0], ep * B0s);
        atomicAdd(&out[HALFSZ + orig * 3 + 1], ep * B1s);
        atomicAdd(&out[HALFSZ + orig * 3 + 2], ep * B2s);
    }
}

extern "C" void kernel_launch(void* const* d_in, const int* in_sizes, int n_in,
                              void* d_out, int out_size) {
    const float* mom = (const float*)d_in[0];            // [1,8192,3]
    const float* control_points = (const float*)d_in[1]; // [1,8192,3]
    float* out = (float*)d_out;                          // [2*8192*3]

    k_hist<<<NHB, HBPTS>>>(control_points, out);
    k_scan<<<1, NCELLS>>>();
    k_scatter<<<NHB, HBPTS>>>(control_points, mom);
    k_main<<<dim3(GXMAIN, JS), TI>>>(out);
}

// round 11
// speedup vs baseline: 1.6937x; 1.6937x over previous
#include <cuda_runtime.h>

// LDDMM Hamiltonian evolve, B=1, N=8192, D=3, sigma=0.1
// out[0:3N]  = -dH/dq = 400 * sum_j K_ij <p_i,p_j> (q_i - q_j)
// out[3N:6N] =  dH/dp = 2   * sum_j K_ij p_j,   K_ij = exp(-100 |q_i-q_j|^2)
//
// R11: 8x8x8 Morton binning, d2 > 0.20 cell culling. Fixes vs R9/R10:
//  - cell pair-bounds prefetched to smem ONCE per CTA (kills per-cell L2 stalls)
//  - survival bitmask computed once per CTA
//  - consecutive surviving cells merged into dense runs (long unrolled loops)
// Inner body: 14 packed f32x2 ops per 2 j at the FFMA2 rt=3 RF-bank floor.

#define NPTS   8192
#define NCELLS 512
#define NBLOCKS 64
#define NHB    16
#define HBPTS  (NPTS / NHB)      // 512
#define PADMAX (NPTS + NCELLS)   // 8704 = 68*128
#define TI     128
#define JS     16
#define NBPC   (NBLOCKS / JS)    // 4 blocks per CTA
#define GXMAIN (PADMAX / TI)     // 68
#define HALFSZ (NPTS * 3)
#define CAP    160               // smem pair capacity per chunk
#define CKER   (-144.26950408889634f)  // -100*log2(e)
#define D2CUT  0.20f

__device__ int   g_cell[NPTS];
__device__ int   g_bh[NHB * NCELLS];
__device__ int   g_boff[NHB * NCELLS];
__device__ int   g_cps[NCELLS + 1];
__device__ int   g_tot;
__device__ float g_pts[(size_t)PADMAX * 8];

typedef unsigned long long u64;

__device__ __forceinline__ u64 pack2(float lo, float hi) {
    u64 r; asm("mov.b64 %0, {%1, %2};" : "=l"(r) : "f"(lo), "f"(hi)); return r;
}
__device__ __forceinline__ void unpack2(u64 v, float& lo, float& hi) {
    asm("mov.b64 {%0, %1}, %2;" : "=f"(lo), "=f"(hi) : "l"(v));
}
__device__ __forceinline__ u64 fma2(u64 a, u64 b, u64 c) {
    u64 r; asm("fma.rn.f32x2 %0, %1, %2, %3;" : "=l"(r) : "l"(a), "l"(b), "l"(c)); return r;
}
__device__ __forceinline__ u64 add2(u64 a, u64 b) {
    u64 r; asm("add.rn.f32x2 %0, %1, %2;" : "=l"(r) : "l"(a), "l"(b)); return r;
}
__device__ __forceinline__ u64 mul2(u64 a, u64 b) {
    u64 r; asm("mul.rn.f32x2 %0, %1, %2;" : "=l"(r) : "l"(a), "l"(b)); return r;
}
__device__ __forceinline__ u64 ex2_2(u64 x) {
    u64 r;
    asm("{\n\t.reg .f32 l, h;\n\t"
        "mov.b64 {l, h}, %1;\n\t"
        "ex2.approx.ftz.f32 l, l;\n\t"
        "ex2.approx.ftz.f32 h, h;\n\t"
        "mov.b64 %0, {l, h};\n\t}" : "=l"(r) : "l"(x));
    return r;
}
__device__ __forceinline__ float fast_ex2(float x) {
    float y; asm("ex2.approx.ftz.f32 %0, %1;" : "=f"(y) : "f"(x)); return y;
}

__device__ __forceinline__ int cell_morton(int cx, int cy, int cz) {
    return (cx & 1) | ((cy & 1) << 1) | ((cz & 1) << 2)
         | ((cx & 2) << 2) | ((cy & 2) << 3) | ((cz & 2) << 4)
         | ((cx & 4) << 4) | ((cy & 4) << 5) | ((cz & 4) << 6);
}
__device__ __forceinline__ void cell_decode(int c, int& cx, int& cy, int& cz) {
    cx = (c & 1) | ((c >> 2) & 2) | ((c >> 4) & 4);
    cy = ((c >> 1) & 1) | ((c >> 3) & 2) | ((c >> 5) & 4);
    cz = ((c >> 2) & 1) | ((c >> 4) & 2) | ((c >> 6) & 4);
}
__device__ __forceinline__ float boxgap2(
    float lox, float hix, float loy, float hiy, float loz, float hiz,
    float blox, float bhix, float bloy, float bhiy, float bloz, float bhiz) {
    float gx = fmaxf(0.f, fmaxf(blox - hix, lox - bhix));
    float gy = fmaxf(0.f, fmaxf(bloy - hiy, loy - bhiy));
    float gz = fmaxf(0.f, fmaxf(bloz - hiz, loz - bhiz));
    return gx * gx + gy * gy + gz * gz;
}

// ---- stage 1: cellid + per-block histogram + zero out ----
__global__ __launch_bounds__(HBPTS)
void k_hist(const float* __restrict__ q, float* __restrict__ out) {
    __shared__ int h[NCELLS];
    const int tid = threadIdx.x;
    const int i = blockIdx.x * HBPTS + tid;
    h[tid] = 0;

    const int v = blockIdx.x * HBPTS + tid;
    reinterpret_cast<float4*>(out)[v] = make_float4(0.f, 0.f, 0.f, 0.f);
    if (v < 4096)
        reinterpret_cast<float4*>(out)[v + 8192] = make_float4(0.f, 0.f, 0.f, 0.f);
    __syncthreads();

    const float x = q[i * 3 + 0], y = q[i * 3 + 1], z = q[i * 3 + 2];
    const int cx = min(7, max(0, (int)(x * 8.0f)));
    const int cy = min(7, max(0, (int)(y * 8.0f)));
    const int cz = min(7, max(0, (int)(z * 8.0f)));
    const int m = cell_morton(cx, cy, cz);
    g_cell[i] = m;
    atomicAdd(&h[m], 1);
    __syncthreads();
    g_bh[blockIdx.x * NCELLS + tid] = h[tid];
}

// ---- stage 2: scan + per-(block,cell) bases + dummy padding ----
__global__ __launch_bounds__(NCELLS)
void k_scan() {
    __shared__ int s[NCELLS];
    const int t = threadIdx.x;

    int part[NHB];
    int cnt = 0;
#pragma unroll
    for (int b = 0; b < NHB; b++) {
        part[b] = cnt;
        cnt += g_bh[b * NCELLS + t];
    }
    const int pc = (cnt + 1) >> 1;
    s[t] = pc;
    __syncthreads();
    for (int off = 1; off < NCELLS; off <<= 1) {
        int v = (t >= off) ? s[t - off] : 0;
        __syncthreads();
        s[t] += v;
        __syncthreads();
    }
    const int excl = s[t] - pc;
    g_cps[t] = excl;
    if (t == NCELLS - 1) {
        g_cps[NCELLS] = s[t];
        g_tot = 2 * s[t];
    }
    const int base = 2 * excl;
#pragma unroll
    for (int b = 0; b < NHB; b++)
        g_boff[b * NCELLS + t] = base + part[b];

    if (cnt & 1) {
        float4* P = reinterpret_cast<float4*>(g_pts);
        const int slot = base + cnt;
        P[slot * 2 + 0] = make_float4(1000.f, 1000.f, 1000.f, CKER * 3.0e6f);
        P[slot * 2 + 1] = make_float4(0.f, 0.f, 0.f, __int_as_float(-1));
    }
}

// ---- stage 3: scatter ----
__global__ __launch_bounds__(HBPTS)
void k_scatter(const float* __restrict__ q, const float* __restrict__ mom) {
    __shared__ int ctr[NCELLS];
    const int tid = threadIdx.x;
    const int i = blockIdx.x * HBPTS + tid;
    ctr[tid] = 0;
    __syncthreads();

    const int c = g_cell[i];
    const int rank = atomicAdd(&ctr[c], 1);
    const int slot = g_boff[blockIdx.x * NCELLS + c] + rank;

    const float cqx = q[i * 3 + 0] - 0.5f;
    const float cqy = q[i * 3 + 1] - 0.5f;
    const float cqz = q[i * 3 + 2] - 0.5f;
    const float sj = CKER * (cqx * cqx + cqy * cqy + cqz * cqz);
    float4* P = reinterpret_cast<float4*>(g_pts);
    P[slot * 2 + 0] = make_float4(cqx, cqy, cqz, sj);
    P[slot * 2 + 1] = make_float4(mom[i * 3 + 0], mom[i * 3 + 1],
                                  mom[i * 3 + 2], __int_as_float(i));
}

// ---- main kernel ----
__global__ __launch_bounds__(TI)
void k_main(float* __restrict__ out) {
    __shared__ __align__(16) u64 s[CAP * 6];
    __shared__ __align__(16) u64 sz[CAP];
    __shared__ float sbb[2][3][4];
    __shared__ int s_cps[NBPC][9];   // cell pair-bounds for my 4 blocks

    const int tid = threadIdx.x;
    const int wid = tid >> 5;
    const int by = blockIdx.y;
    const int i = blockIdx.x * TI + tid;
    const int tot = g_tot;
    const float4* P = reinterpret_cast<const float4*>(g_pts);

    // One-time prefetch of all needed cell bounds (36 ints, coalesced)
    for (int k = tid; k < NBPC * 9; k += TI) {
        const int blk = k / 9, cc = k % 9;
        s_cps[blk][cc] = g_cps[(by + JS * blk) * 8 + cc];
    }

    const float4 a0 = P[(size_t)i * 2 + 0];
    const float4 a1 = P[(size_t)i * 2 + 1];
    const float cqx = a0.x, cqy = a0.y, cqz = a0.z;
    const float px = a1.x, py = a1.y, pz = a1.z;
    const int orig = __float_as_int(a1.w);
    const bool use = (i < tot) && (orig >= 0);

    {
        float vx[3] = {use ? cqx : 1e30f, use ? cqy : 1e30f, use ? cqz : 1e30f};
        float wx[3] = {use ? cqx : -1e30f, use ? cqy : -1e30f, use ? cqz : -1e30f};
#pragma unroll
        for (int k = 0; k < 3; k++) {
#pragma unroll
            for (int o = 16; o; o >>= 1) {
                vx[k] = fminf(vx[k], __shfl_xor_sync(0xFFFFFFFFu, vx[k], o));
                wx[k] = fmaxf(wx[k], __shfl_xor_sync(0xFFFFFFFFu, wx[k], o));
            }
            if ((tid & 31) == 0) { sbb[0][k][wid] = vx[k]; sbb[1][k][wid] = wx[k]; }
        }
    }
    __syncthreads();
    const float ilox = fminf(fminf(sbb[0][0][0], sbb[0][0][1]), fminf(sbb[0][0][2], sbb[0][0][3]));
    const float iloy = fminf(fminf(sbb[0][1][0], sbb[0][1][1]), fminf(sbb[0][1][2], sbb[0][1][3]));
    const float iloz = fminf(fminf(sbb[0][2][0], sbb[0][2][1]), fminf(sbb[0][2][2], sbb[0][2][3]));
    const float ihix = fmaxf(fmaxf(sbb[1][0][0], sbb[1][0][1]), fmaxf(sbb[1][0][2], sbb[1][0][3]));
    const float ihiy = fmaxf(fmaxf(sbb[1][1][0], sbb[1][1][1]), fmaxf(sbb[1][1][2], sbb[1][1][3]));
    const float ihiz = fmaxf(fmaxf(sbb[1][2][0], sbb[1][2][1]), fmaxf(sbb[1][2][2], sbb[1][2][3]));

    // Survival bitmask per block (uniform across CTA), computed once.
    int mask[NBPC];
#pragma unroll
    for (int blk = 0; blk < NBPC; blk++) {
        const int b = by + JS * blk;
        int m = 0;
#pragma unroll
        for (int cc = 0; cc < 8; cc++) {
            int cx, cy, cz;
            cell_decode(b * 8 + cc, cx, cy, cz);
            const float clox = cx * 0.125f - 0.5f;
            const float cloy = cy * 0.125f - 0.5f;
            const float cloz = cz * 0.125f - 0.5f;
            if (boxgap2(ilox, ihix, iloy, ihiy, iloz, ihiz,
                        clox, clox + 0.125f, cloy, cloy + 0.125f,
                        cloz, cloz + 0.125f) <= D2CUT)
                m |= (1 << cc);
        }
        mask[blk] = m;
    }

    const u64 M2X = pack2(-2.0f * CKER * cqx, -2.0f * CKER * cqx);
    const u64 M2Y = pack2(-2.0f * CKER * cqy, -2.0f * CKER * cqy);
    const u64 M2Z = pack2(-2.0f * CKER * cqz, -2.0f * CKER * cqz);
    const u64 PXX = pack2(px, px), PYY = pack2(py, py), PZZ = pack2(pz, pz);

    u64 B0 = 0, B1 = 0, B2 = 0, A0 = 0, A1 = 0, A2 = 0, W = 0;

#pragma unroll 1
    for (int blk = 0; blk < NBPC; blk++) {
        const int m = mask[blk];
        if (m == 0) continue;

        // pair range covering surviving cells only
        const int cFirst = __ffs(m) - 1;
        const int cLast = 31 - __clz(m);
        int ps = s_cps[blk][cFirst];
        const int pe = s_cps[blk][cLast + 1];

        while (ps < pe) {
            const int n = min(pe - ps, CAP);
            for (int t = tid; t < n; t += TI) {
                const int pp = ps + t;
                const float4 j0a = P[(size_t)(2 * pp) * 2 + 0];
                const float4 j0b = P[(size_t)(2 * pp) * 2 + 1];
                const float4 j1a = P[(size_t)(2 * pp + 1) * 2 + 0];
                const float4 j1b = P[(size_t)(2 * pp + 1) * 2 + 1];
                s[t * 6 + 0] = pack2(j0a.x, j1a.x);
                s[t * 6 + 1] = pack2(j0a.y, j1a.y);
                s[t * 6 + 2] = pack2(j0a.z, j1a.z);
                s[t * 6 + 3] = pack2(j0a.w, j1a.w);
                s[t * 6 + 4] = pack2(j0b.x, j1b.x);
                s[t * 6 + 5] = pack2(j0b.y, j1b.y);
                sz[t]        = pack2(j0b.z, j1b.z);
            }
            __syncthreads();

            // iterate runs of consecutive surviving cells (bounds from smem)
            int cc = cFirst;
            while (cc <= cLast) {
                if (!(m & (1 << cc))) { cc++; continue; }
                const int cs = cc;
                while (cc < 8 && (m & (1 << cc))) cc++;
                const int lo = max(s_cps[blk][cs], ps) - ps;
                const int hi = min(s_cps[blk][cc], ps + n) - ps;

#pragma unroll 2
                for (int p = lo; p < hi; p++) {
                    const ulonglong2 w0 = *reinterpret_cast<const ulonglong2*>(&s[p * 6 + 0]);
                    const ulonglong2 w1 = *reinterpret_cast<const ulonglong2*>(&s[p * 6 + 2]);
                    const ulonglong2 w2 = *reinterpret_cast<const ulonglong2*>(&s[p * 6 + 4]);
                    const u64 mz = sz[p];
                    const u64 jx = w0.x, jy = w0.y, jz = w1.x, sj = w1.y;
                    const u64 mx = w2.x, my = w2.y;

                    u64 t = fma2(jx, M2X, sj);
                    t = fma2(jy, M2Y, t);
                    t = fma2(jz, M2Z, t);
                    const u64 K = ex2_2(t);

                    const u64 pd = fma2(PXX, mx, fma2(PYY, my, mul2(PZZ, mz)));

                    B0 = fma2(K, mx, B0);
                    B1 = fma2(K, my, B1);
                    B2 = fma2(K, mz, B2);

                    const u64 w = mul2(K, pd);
                    W  = add2(W, w);
                    A0 = fma2(w, jx, A0);
                    A1 = fma2(w, jy, A1);
                    A2 = fma2(w, jz, A2);
                }
            }
            __syncthreads();
            ps += n;
        }
    }

    if (use) {
        const float Ei = fast_ex2(CKER * (cqx * cqx + cqy * cqy + cqz * cqz));
        const float eq = 400.0f * Ei, ep = 2.0f * Ei;
        float l, h, Ws, A0s, A1s, A2s, B0s, B1s, B2s;
        unpack2(W,  l, h); Ws  = l + h;
        unpack2(A0, l, h); A0s = l + h;
        unpack2(A1, l, h); A1s = l + h;
        unpack2(A2, l, h); A2s = l + h;
        unpack2(B0, l, h); B0s = l + h;
        unpack2(B1, l, h); B1s = l + h;
        unpack2(B2, l, h); B2s = l + h;
        atomicAdd(&out[orig * 3 + 0], eq * fmaf(Ws, cqx, -A0s));
        atomicAdd(&out[orig * 3 + 1], eq * fmaf(Ws, cqy, -A1s));
        atomicAdd(&out[orig * 3 + 2], eq * fmaf(Ws, cqz, -A2s));
        atomicAdd(&out[HALFSZ + orig * 3 + 0], ep * B0s);
        atomicAdd(&out[HALFSZ + orig * 3 + 1], ep * B1s);
        atomicAdd(&out[HALFSZ + orig * 3 + 2], ep * B2s);
    }
}

extern "C" void kernel_launch(void* const* d_in, const int* in_sizes, int n_in,
                              void* d_out, int out_size) {
    const float* mom = (const float*)d_in[0];            // [1,8192,3]
    const float* control_points = (const float*)d_in[1]; // [1,8192,3]
    float* out = (float*)d_out;                          // [2*8192*3]

    k_hist<<<NHB, HBPTS>>>(control_points, out);
    k_scan<<<1, NCELLS>>>();
    k_scatter<<<NHB, HBPTS>>>(control_points, mom);
    k_main<<<dim3(GXMAIN, JS), TI>>>(out);
}